// round 1
// baseline (speedup 1.0000x reference)
#include <cuda_runtime.h>
#include <math.h>

#define VOL   128
#define VOL2  (VOL*VOL)
#define VOL3  (VOL*VOL*VOL)
#define NB    4
#define NVOX  (NB*VOL3)       // 8388608
#define OT    26              // output tile (x,y) per block
#define NT    5               // ceil(128/26)
#define ZS    2               // z segments per volume
#define ZRANGE (VOL/ZS)       // 64

#define PINF __int_as_float(0x7f800000)
#define NINF __int_as_float(0xff800000)

// Scratch (device-global: allocation-free rule)
__device__ float g_yp[NVOX];     // sigmoid(y_pred)
__device__ float g_imgA[NVOX];   // ping
__device__ float g_imgB[NVOX];   // pong
__device__ float g_skel[NVOX];   // current skeleton
__device__ float g_acc[8];       // 0:sum_t 1:sum_p 2:sum_tp 3:sum_skp 4:sum_skp_t 5:sum_skt 6:sum_skt_p

__device__ __forceinline__ const float* pick(int sel, const float* ext) {
    if (sel == 0) return g_imgA;
    if (sel == 1) return g_imgB;
    if (sel == 2) return g_yp;
    return ext;
}

__global__ void zero_acc_kernel() {
    if (threadIdx.x < 8) g_acc[threadIdx.x] = 0.f;
}

// ---------------------------------------------------------------------------
// prep: yp = sigmoid(pred); accumulate sum(true), sum(yp), sum(true*yp)
// ---------------------------------------------------------------------------
__global__ __launch_bounds__(256) void prep_kernel(const float* __restrict__ pred,
                                                   const float* __restrict__ tru) {
    __shared__ float sm[3][8];
    int base = blockIdx.x * 2048 + threadIdx.x;
    float st = 0.f, sp = 0.f, stp = 0.f;
#pragma unroll
    for (int k = 0; k < 8; k++) {
        int i = base + k * 256;
        float t = tru[i];
        float x = pred[i];
        float p = 1.f / (1.f + expf(-x));
        g_yp[i] = p;
        st += t; sp += p; stp += t * p;
    }
#pragma unroll
    for (int o = 16; o > 0; o >>= 1) {
        st  += __shfl_xor_sync(0xffffffffu, st,  o);
        sp  += __shfl_xor_sync(0xffffffffu, sp,  o);
        stp += __shfl_xor_sync(0xffffffffu, stp, o);
    }
    int w = threadIdx.x >> 5, lane = threadIdx.x & 31;
    if (lane == 0) { sm[0][w] = st; sm[1][w] = sp; sm[2][w] = stp; }
    __syncthreads();
    if (threadIdx.x == 0) {
        float a = 0.f, b = 0.f, c = 0.f;
#pragma unroll
        for (int i = 0; i < 8; i++) { a += sm[0][i]; b += sm[1][i]; c += sm[2][i]; }
        atomicAdd(&g_acc[0], a); atomicAdd(&g_acc[1], b); atomicAdd(&g_acc[2], c);
    }
}

// ---------------------------------------------------------------------------
// init: skel = relu(x - dilate(erode(x)))   (radius-2 z-sweep pipeline)
// ---------------------------------------------------------------------------
__global__ __launch_bounds__(1024, 2) void init_kernel(int inSel, const float* __restrict__ extIn) {
    __shared__ float As[32][33];
    __shared__ float Es[32][33];
    const float* __restrict__ x = pick(inSel, extIn);

    const int tx = threadIdx.x, ty = threadIdx.y;
    const int b   = blockIdx.z >> 1;
    const int oz0 = (blockIdx.z & 1) * ZRANGE;
    const int oz1 = oz0 + ZRANGE;
    const int gx = blockIdx.x * OT - 3 + tx;
    const int gy = blockIdx.y * OT - 3 + ty;
    const bool v  = (gx >= 0 && gx < VOL && gy >= 0 && gy < VOL);
    const bool wr = v && tx >= 3 && tx < 29 && ty >= 3 && ty < 29;
    const int xm = tx > 0 ? tx - 1 : 0,  xp = tx < 31 ? tx + 1 : 31;
    const int ym = ty > 0 ? ty - 1 : 0,  yp2 = ty < 31 ? ty + 1 : 31;
    const int colOff = v ? (gy * VOL + gx) : 0;
    const int bOff = b * VOL3;

    float a_m1 = PINF, a_m2 = PINF, bxy_m1 = PINF;
    float m_m1 = NINF, m_m2 = NINF;

    for (int z = oz0 - 2; z <= oz1 + 1; ++z) {
        float aP = PINF;
        if (v && (unsigned)z < (unsigned)VOL) aP = x[bOff + z * VOL2 + colOff];
        As[ty][tx] = aP;
        __syncthreads();
        float bxy = fminf(fminf(As[ty][xm], As[ty][xp]),
                          fminf(As[ym][tx], fminf(As[yp2][tx], aP)));
        float e1 = fminf(fminf(a_m2, aP), bxy_m1);          // e1(z-1)
        if (!v || (unsigned)(z - 1) >= (unsigned)VOL) e1 = NINF;  // -inf pad for dilate
        Es[ty][tx] = e1;
        __syncthreads();
        float r0 = fmaxf(fmaxf(Es[ym][xm], Es[ym][tx]), Es[ym][xp]);
        float r1 = fmaxf(fmaxf(Es[ty][xm], e1), Es[ty][xp]);
        float r2 = fmaxf(fmaxf(Es[yp2][xm], Es[yp2][tx]), Es[yp2][xp]);
        float mxy = fmaxf(fmaxf(r0, r1), r2);               // mxy(z-1)
        int zo = z - 2;
        if (wr && zo >= oz0 && zo < oz1) {
            float openv = fmaxf(fmaxf(m_m2, m_m1), mxy);    // dilate at zo
            int gi = bOff + zo * VOL2 + colOff;
            g_skel[gi] = fmaxf(a_m2 - openv, 0.f);          // a_m2 = x(zo)
        }
        a_m2 = a_m1; a_m1 = aP; bxy_m1 = bxy;
        m_m2 = m_m1; m_m1 = mxy;
    }
}

// ---------------------------------------------------------------------------
// iter: img' = erode(img); open = dilate(erode(img')); skel update.
// Radius-3 fused z-sweep pipeline. Optionally accumulates final sums.
// ---------------------------------------------------------------------------
__global__ __launch_bounds__(1024, 2) void iter_kernel(
    int inSel, const float* __restrict__ extIn, int outSel,
    int doSum, int otherSel, const float* __restrict__ extOther, int accBase)
{
    __shared__ float As[32][33];
    __shared__ float Es[32][33];
    __shared__ float E2s[32][33];
    const float* __restrict__ imgIn = pick(inSel, extIn);
    float* imgOut = (outSel == 0) ? g_imgA : g_imgB;
    const float* __restrict__ other = pick(otherSel, extOther);

    const int tx = threadIdx.x, ty = threadIdx.y;
    const int b   = blockIdx.z >> 1;
    const int oz0 = (blockIdx.z & 1) * ZRANGE;
    const int oz1 = oz0 + ZRANGE;
    const int gx = blockIdx.x * OT - 3 + tx;
    const int gy = blockIdx.y * OT - 3 + ty;
    const bool v  = (gx >= 0 && gx < VOL && gy >= 0 && gy < VOL);
    const bool wr = v && tx >= 3 && tx < 29 && ty >= 3 && ty < 29;
    const int xm = tx > 0 ? tx - 1 : 0,  xp = tx < 31 ? tx + 1 : 31;
    const int ym = ty > 0 ? ty - 1 : 0,  yp2 = ty < 31 ? ty + 1 : 31;
    const int colOff = v ? (gy * VOL + gx) : 0;
    const int bOff = b * VOL3;

    float a_m1 = PINF, a_m2 = PINF, bxy_m1 = PINF;
    float e1_m1 = PINF, e1_m2 = PINF, cxy_m1 = PINF;
    float m_m1 = NINF, m_m2 = NINF;
    float sumS = 0.f, sumC = 0.f;

    for (int z = oz0 - 3; z <= oz1 + 2; ++z) {
        float aP = PINF;
        if (v && (unsigned)z < (unsigned)VOL) aP = imgIn[bOff + z * VOL2 + colOff];
        As[ty][tx] = aP;
        __syncthreads();
        float bxy = fminf(fminf(As[ty][xm], As[ty][xp]),
                          fminf(As[ym][tx], fminf(As[yp2][tx], aP)));
        float e1 = fminf(fminf(a_m2, aP), bxy_m1);          // e1(z-1) = erode(img)
        if (!v || (unsigned)(z - 1) >= (unsigned)VOL) e1 = PINF;  // +inf pad for 2nd erode
        Es[ty][tx] = e1;
        __syncthreads();
        float cxy = fminf(fminf(Es[ty][xm], Es[ty][xp]),
                          fminf(Es[ym][tx], fminf(Es[yp2][tx], e1)));
        float e2 = fminf(fminf(e1_m2, e1), cxy_m1);         // e2(z-2) = erode(e1)
        if (!v || (unsigned)(z - 2) >= (unsigned)VOL) e2 = NINF;  // -inf pad for dilate
        E2s[ty][tx] = e2;
        __syncthreads();
        float r0 = fmaxf(fmaxf(E2s[ym][xm], E2s[ym][tx]), E2s[ym][xp]);
        float r1 = fmaxf(fmaxf(E2s[ty][xm], e2), E2s[ty][xp]);
        float r2 = fmaxf(fmaxf(E2s[yp2][xm], E2s[yp2][tx]), E2s[yp2][xp]);
        float mxy = fmaxf(fmaxf(r0, r1), r2);               // mxy(z-2)
        int zo = z - 3;
        if (wr && zo >= oz0 && zo < oz1) {
            float openv = fmaxf(fmaxf(m_m2, m_m1), mxy);    // dilate(e2) at zo
            float imgN = e1_m2;                             // e1(zo) = new img
            float delta = fmaxf(imgN - openv, 0.f);
            int gi = bOff + zo * VOL2 + colOff;
            float s = g_skel[gi];
            s += fmaxf(fmaf(-s, delta, delta), 0.f);        // skel += relu(delta - skel*delta)
            g_skel[gi] = s;
            imgOut[gi] = imgN;
            if (doSum) { sumS += s; sumC += s * other[gi]; }
        }
        a_m2 = a_m1; a_m1 = aP; bxy_m1 = bxy;
        e1_m2 = e1_m1; e1_m1 = e1; cxy_m1 = cxy;
        m_m2 = m_m1; m_m1 = mxy;
    }

    if (doSum) {
        __syncthreads();
#pragma unroll
        for (int o = 16; o > 0; o >>= 1) {
            sumS += __shfl_xor_sync(0xffffffffu, sumS, o);
            sumC += __shfl_xor_sync(0xffffffffu, sumC, o);
        }
        int tid = ty * 32 + tx;
        int w = tid >> 5, lane = tid & 31;
        if (lane == 0) { As[0][w] = sumS; Es[0][w] = sumC; }
        __syncthreads();
        if (w == 0) {
            float s = As[0][lane], c = Es[0][lane];
#pragma unroll
            for (int o = 16; o > 0; o >>= 1) {
                s += __shfl_xor_sync(0xffffffffu, s, o);
                c += __shfl_xor_sync(0xffffffffu, c, o);
            }
            if (lane == 0) {
                atomicAdd(&g_acc[accBase], s);
                atomicAdd(&g_acc[accBase + 1], c);
            }
        }
    }
}

// ---------------------------------------------------------------------------
// finalize scalar
// ---------------------------------------------------------------------------
__global__ void final_kernel(float* out) {
    float st = g_acc[0], sp = g_acc[1], stp = g_acc[2];
    float skp = g_acc[3], skpt = g_acc[4], skt = g_acc[5], sktp = g_acc[6];
    float dice = 1.f - (2.f * stp + 1.f) / (st + sp + 1.f);
    float tprec = (skpt + 1.f) / (skp + 1.f);
    float tsens = (sktp + 1.f) / (skt + 1.f);
    float cl = 1.f - 2.f * (tprec * tsens) / (tprec + tsens);
    out[0] = 0.7f * dice + 0.3f * cl;
}

extern "C" void kernel_launch(void* const* d_in, const int* in_sizes, int n_in,
                              void* d_out, int out_size) {
    const float* pred = (const float*)d_in[0];
    const float* tru  = (const float*)d_in[1];
    float* out = (float*)d_out;

    dim3 blk(32, 32);
    dim3 grd(NT, NT, ZS * NB);

    zero_acc_kernel<<<1, 32>>>();
    prep_kernel<<<NVOX / 2048, 256>>>(pred, tru);

    // ---- pred skeleton (x = sigmoid(pred) in g_yp) ----
    init_kernel<<<grd, blk>>>(2, nullptr);
    iter_kernel<<<grd, blk>>>(2, nullptr, 0, 0, 0, nullptr, 0);      // iter 1: yp -> A
    for (int k = 2; k <= 16; ++k) {
        int inSel  = (k & 1) ? 1 : 0;
        int outSel = (k & 1) ? 0 : 1;
        int doSum  = (k == 16) ? 1 : 0;
        iter_kernel<<<grd, blk>>>(inSel, nullptr, outSel, doSum, 3, tru, 3);
    }

    // ---- true skeleton (x = y_true) ----
    init_kernel<<<grd, blk>>>(3, tru);
    iter_kernel<<<grd, blk>>>(3, tru, 0, 0, 0, nullptr, 0);          // iter 1: tru -> A
    for (int k = 2; k <= 16; ++k) {
        int inSel  = (k & 1) ? 1 : 0;
        int outSel = (k & 1) ? 0 : 1;
        int doSum  = (k == 16) ? 1 : 0;
        iter_kernel<<<grd, blk>>>(inSel, nullptr, outSel, doSum, 2, nullptr, 5);
    }

    final_kernel<<<1, 1>>>(out);
}

// round 2
// speedup vs baseline: 1.9074x; 1.9074x over previous
#include <cuda_runtime.h>
#include <math.h>

#define VOL   128
#define VOL2  (VOL*VOL)
#define VOL3  (VOL*VOL*VOL)
#define NB    4
#define NVOX  (NB*VOL3)
#define OTY   26              // output rows per block tile (y)
#define NTY   5               // ceil(128/26)
#define ZSEG  8               // z segments per volume
#define ZLEN  (VOL/ZSEG)      // 16

#define PINF __int_as_float(0x7f800000)
#define NINF __int_as_float(0xff800000)

__device__ float g_yp[NVOX];
__device__ float g_imgA[NVOX];
__device__ float g_imgB[NVOX];
__device__ float g_skel[NVOX];
__device__ float g_acc[8];

__device__ __forceinline__ const float* pick(int sel, const float* ext) {
    if (sel == 0) return g_imgA;
    if (sel == 1) return g_imgB;
    if (sel == 2) return g_yp;
    return ext;
}

__device__ __forceinline__ float4 f4(float v) { return make_float4(v, v, v, v); }
__device__ __forceinline__ float4 vmin(float4 a, float4 b) {
    return make_float4(fminf(a.x,b.x), fminf(a.y,b.y), fminf(a.z,b.z), fminf(a.w,b.w));
}
__device__ __forceinline__ float4 vmax(float4 a, float4 b) {
    return make_float4(fmaxf(a.x,b.x), fmaxf(a.y,b.y), fmaxf(a.z,b.z), fmaxf(a.w,b.w));
}
__device__ __forceinline__ float4 vmin3(float4 a, float4 b, float4 c) { return vmin(vmin(a,b),c); }
__device__ __forceinline__ float4 vmax3(float4 a, float4 b, float4 c) { return vmax(vmax(a,b),c); }

// horizontal min over [x-1,x+1] per element; x-clamp at volume edges (lane 0/31)
__device__ __forceinline__ float4 hmin_shfl(float4 a, int tx) {
    float aL = __shfl_up_sync(0xffffffffu, a.w, 1);
    float aR = __shfl_down_sync(0xffffffffu, a.x, 1);
    if (tx == 0)  aL = a.x;
    if (tx == 31) aR = a.w;
    float m01 = fminf(a.x, a.y), m12 = fminf(a.y, a.z), m23 = fminf(a.z, a.w);
    return make_float4(fminf(aL, m01), fminf(m01, a.z), fminf(m12, a.w), fminf(m23, aR));
}
__device__ __forceinline__ float4 hmax_shfl(float4 a, int tx) {
    float aL = __shfl_up_sync(0xffffffffu, a.w, 1);
    float aR = __shfl_down_sync(0xffffffffu, a.x, 1);
    if (tx == 0)  aL = a.x;
    if (tx == 31) aR = a.w;
    float m01 = fmaxf(a.x, a.y), m12 = fmaxf(a.y, a.z), m23 = fmaxf(a.z, a.w);
    return make_float4(fmaxf(aL, m01), fmaxf(m01, a.z), fmaxf(m12, a.w), fmaxf(m23, aR));
}

__global__ void zero_acc_kernel() {
    if (threadIdx.x < 8) g_acc[threadIdx.x] = 0.f;
}

// ---------------------------------------------------------------------------
// prep: yp = sigmoid(pred); sums for dice (float4 vectorized)
// ---------------------------------------------------------------------------
__global__ __launch_bounds__(256) void prep_kernel(const float* __restrict__ pred,
                                                   const float* __restrict__ tru) {
    __shared__ float sm[3][8];
    const float4* p4 = (const float4*)pred;
    const float4* t4 = (const float4*)tru;
    float4* y4 = (float4*)g_yp;
    int base = blockIdx.x * 1024 + threadIdx.x;
    float st = 0.f, sp = 0.f, stp = 0.f;
#pragma unroll
    for (int k = 0; k < 4; k++) {
        int i = base + k * 256;
        float4 t = t4[i];
        float4 x = p4[i];
        float4 p;
        p.x = 1.f / (1.f + __expf(-x.x));
        p.y = 1.f / (1.f + __expf(-x.y));
        p.z = 1.f / (1.f + __expf(-x.z));
        p.w = 1.f / (1.f + __expf(-x.w));
        y4[i] = p;
        st  += (t.x + t.y) + (t.z + t.w);
        sp  += (p.x + p.y) + (p.z + p.w);
        stp += (t.x*p.x + t.y*p.y) + (t.z*p.z + t.w*p.w);
    }
#pragma unroll
    for (int o = 16; o > 0; o >>= 1) {
        st  += __shfl_xor_sync(0xffffffffu, st,  o);
        sp  += __shfl_xor_sync(0xffffffffu, sp,  o);
        stp += __shfl_xor_sync(0xffffffffu, stp, o);
    }
    int w = threadIdx.x >> 5, lane = threadIdx.x & 31;
    if (lane == 0) { sm[0][w] = st; sm[1][w] = sp; sm[2][w] = stp; }
    __syncthreads();
    if (threadIdx.x == 0) {
        float a = 0.f, b = 0.f, c = 0.f;
#pragma unroll
        for (int i = 0; i < 8; i++) { a += sm[0][i]; b += sm[1][i]; c += sm[2][i]; }
        atomicAdd(&g_acc[0], a); atomicAdd(&g_acc[1], b); atomicAdd(&g_acc[2], c);
    }
}

// ---------------------------------------------------------------------------
// init: skel = relu(x - dilate(erode(x)))   float4 z-sweep, radius 2
// ---------------------------------------------------------------------------
__global__ __launch_bounds__(1024) void init_kernel(int inSel, const float* __restrict__ extIn) {
    __shared__ float4 As[32][32];
    __shared__ float4 Ms[32][32];
    const float* __restrict__ x = pick(inSel, extIn);

    const int tx = threadIdx.x, ty = threadIdx.y;
    const int b   = blockIdx.z;
    const int oz0 = blockIdx.y * ZLEN;
    const int oz1 = oz0 + ZLEN;
    const int gy  = blockIdx.x * OTY - 3 + ty;
    const bool vrow = (gy >= 0 && gy < VOL);
    const bool wr   = vrow && ty >= 3 && ty < 29;
    const int ym = ty > 0 ? ty - 1 : 0, yp = ty < 31 ? ty + 1 : 31;
    const int bOff = b * VOL3;
    const int rowOff = bOff + (vrow ? gy : 0) * VOL + tx * 4;

    float4 a_m1 = f4(PINF), a_m2 = f4(PINF), bxy_m1 = f4(PINF);
    float4 m_m1 = f4(NINF), m_m2 = f4(NINF);

    int z0 = oz0 - 2;
    float4 cur = f4(PINF);
    if (vrow && (unsigned)z0 < (unsigned)VOL)
        cur = *(const float4*)(x + z0 * VOL2 + rowOff);

    for (int z = z0; z <= oz1 + 1; ++z) {
        float4 nxt = f4(PINF);
        if (vrow && (unsigned)(z + 1) < (unsigned)VOL)
            nxt = *(const float4*)(x + (z + 1) * VOL2 + rowOff);

        As[ty][tx] = cur;
        __syncthreads();
        float4 up = As[ym][tx], dn = As[yp][tx];
        float4 h  = hmin_shfl(cur, tx);
        float4 bxy = vmin3(h, up, dn);
        float4 e1 = vmin3(a_m2, cur, bxy_m1);              // erode at z-1
        if (!vrow || (unsigned)(z - 1) >= (unsigned)VOL) e1 = f4(NINF);
        float4 hm = hmax_shfl(e1, tx);
        __syncthreads();
        Ms[ty][tx] = hm;
        __syncthreads();
        float4 mxy = vmax3(hm, Ms[ym][tx], Ms[yp][tx]);    // 3x3 max of e1 at z-1
        int zo = z - 2;
        if (wr && zo >= oz0 && zo < oz1) {
            float4 openv = vmax3(m_m2, m_m1, mxy);
            float4 s;
            s.x = fmaxf(a_m2.x - openv.x, 0.f);
            s.y = fmaxf(a_m2.y - openv.y, 0.f);
            s.z = fmaxf(a_m2.z - openv.z, 0.f);
            s.w = fmaxf(a_m2.w - openv.w, 0.f);
            *(float4*)(g_skel + zo * VOL2 + rowOff) = s;
        }
        a_m2 = a_m1; a_m1 = cur; bxy_m1 = bxy;
        m_m2 = m_m1; m_m1 = mxy;
        cur = nxt;
    }
}

// ---------------------------------------------------------------------------
// iter: img' = erode(img); open = dilate(erode(img')); skel update
// float4 z-sweep pipeline, radius 3, shuffles for x, .128 shared for y
// ---------------------------------------------------------------------------
__global__ __launch_bounds__(1024) void iter_kernel(
    int inSel, const float* __restrict__ extIn, int outSel,
    int doSum, int otherSel, const float* __restrict__ extOther, int accBase)
{
    __shared__ float4 As[32][32];
    __shared__ float4 Es[32][32];
    __shared__ float4 Ms[32][32];
    const float* __restrict__ imgIn = pick(inSel, extIn);
    float* imgOut = (outSel == 0) ? g_imgA : g_imgB;
    const float* __restrict__ other = pick(otherSel, extOther);

    const int tx = threadIdx.x, ty = threadIdx.y;
    const int b   = blockIdx.z;
    const int oz0 = blockIdx.y * ZLEN;
    const int oz1 = oz0 + ZLEN;
    const int gy  = blockIdx.x * OTY - 3 + ty;
    const bool vrow = (gy >= 0 && gy < VOL);
    const bool wr   = vrow && ty >= 3 && ty < 29;
    const int ym = ty > 0 ? ty - 1 : 0, yp = ty < 31 ? ty + 1 : 31;
    const int bOff = b * VOL3;
    const int rowOff = bOff + (vrow ? gy : 0) * VOL + tx * 4;

    float4 a_m1 = f4(PINF), a_m2 = f4(PINF), bxy_m1 = f4(PINF);
    float4 e1_m1 = f4(PINF), e1_m2 = f4(PINF), cxy_m1 = f4(PINF);
    float4 m_m1 = f4(NINF), m_m2 = f4(NINF);
    float sumS = 0.f, sumC = 0.f;

    int z0 = oz0 - 3;
    float4 cur = f4(PINF);
    if (vrow && (unsigned)z0 < (unsigned)VOL)
        cur = *(const float4*)(imgIn + z0 * VOL2 + rowOff);

    for (int z = z0; z <= oz1 + 2; ++z) {
        float4 nxt = f4(PINF);
        if (vrow && (unsigned)(z + 1) < (unsigned)VOL)
            nxt = *(const float4*)(imgIn + (z + 1) * VOL2 + rowOff);

        // stage 1: erode(img) at z-1
        As[ty][tx] = cur;
        __syncthreads();
        float4 up = As[ym][tx], dn = As[yp][tx];
        float4 h  = hmin_shfl(cur, tx);
        float4 bxy = vmin3(h, up, dn);
        float4 e1 = vmin3(a_m2, cur, bxy_m1);
        if (!vrow || (unsigned)(z - 1) >= (unsigned)VOL) e1 = f4(PINF);

        // stage 2: erode(e1) at z-2
        Es[ty][tx] = e1;
        __syncthreads();
        float4 upe = Es[ym][tx], dne = Es[yp][tx];
        float4 h2  = hmin_shfl(e1, tx);
        float4 cxy = vmin3(h2, upe, dne);
        float4 e2 = vmin3(e1_m2, e1, cxy_m1);
        if (!vrow || (unsigned)(z - 2) >= (unsigned)VOL) e2 = f4(NINF);

        // stage 3: 3x3 in-plane max of e2 (store row-hmax, combine rows)
        float4 hm = hmax_shfl(e2, tx);
        Ms[ty][tx] = hm;
        __syncthreads();
        float4 mxy = vmax3(hm, Ms[ym][tx], Ms[yp][tx]);

        int zo = z - 3;
        if (wr && zo >= oz0 && zo < oz1) {
            float4 openv = vmax3(m_m2, m_m1, mxy);          // dilate(e2) at zo
            float4 imgN = e1_m2;                            // erode(img) at zo
            float4 delta;
            delta.x = fmaxf(imgN.x - openv.x, 0.f);
            delta.y = fmaxf(imgN.y - openv.y, 0.f);
            delta.z = fmaxf(imgN.z - openv.z, 0.f);
            delta.w = fmaxf(imgN.w - openv.w, 0.f);
            int gi = zo * VOL2 + rowOff;
            float4 s = *(float4*)(g_skel + gi);
            s.x += fmaxf(fmaf(-s.x, delta.x, delta.x), 0.f);
            s.y += fmaxf(fmaf(-s.y, delta.y, delta.y), 0.f);
            s.z += fmaxf(fmaf(-s.z, delta.z, delta.z), 0.f);
            s.w += fmaxf(fmaf(-s.w, delta.w, delta.w), 0.f);
            *(float4*)(g_skel + gi) = s;
            *(float4*)(imgOut + gi) = imgN;
            if (doSum) {
                float4 o = *(const float4*)(other + gi);
                sumS += (s.x + s.y) + (s.z + s.w);
                sumC += (s.x*o.x + s.y*o.y) + (s.z*o.z + s.w*o.w);
            }
        }
        a_m2 = a_m1; a_m1 = cur; bxy_m1 = bxy;
        e1_m2 = e1_m1; e1_m1 = e1; cxy_m1 = cxy;
        m_m2 = m_m1; m_m1 = mxy;
        cur = nxt;
    }

    if (doSum) {
        __syncthreads();
#pragma unroll
        for (int o = 16; o > 0; o >>= 1) {
            sumS += __shfl_xor_sync(0xffffffffu, sumS, o);
            sumC += __shfl_xor_sync(0xffffffffu, sumC, o);
        }
        int tid = ty * 32 + tx;
        int w = tid >> 5, lane = tid & 31;
        float* red = (float*)As;
        if (lane == 0) { red[w] = sumS; red[32 + w] = sumC; }
        __syncthreads();
        if (w == 0) {
            float s = red[lane], c = red[32 + lane];
#pragma unroll
            for (int o = 16; o > 0; o >>= 1) {
                s += __shfl_xor_sync(0xffffffffu, s, o);
                c += __shfl_xor_sync(0xffffffffu, c, o);
            }
            if (lane == 0) {
                atomicAdd(&g_acc[accBase], s);
                atomicAdd(&g_acc[accBase + 1], c);
            }
        }
    }
}

__global__ void final_kernel(float* out) {
    float st = g_acc[0], sp = g_acc[1], stp = g_acc[2];
    float skp = g_acc[3], skpt = g_acc[4], skt = g_acc[5], sktp = g_acc[6];
    float dice = 1.f - (2.f * stp + 1.f) / (st + sp + 1.f);
    float tprec = (skpt + 1.f) / (skp + 1.f);
    float tsens = (sktp + 1.f) / (skt + 1.f);
    float cl = 1.f - 2.f * (tprec * tsens) / (tprec + tsens);
    out[0] = 0.7f * dice + 0.3f * cl;
}

extern "C" void kernel_launch(void* const* d_in, const int* in_sizes, int n_in,
                              void* d_out, int out_size) {
    const float* pred = (const float*)d_in[0];
    const float* tru  = (const float*)d_in[1];
    float* out = (float*)d_out;

    dim3 blk(32, 32);
    dim3 grd(NTY, ZSEG, NB);

    zero_acc_kernel<<<1, 32>>>();
    prep_kernel<<<NVOX / 4096, 256>>>(pred, tru);

    // ---- pred skeleton (x = sigmoid(pred) in g_yp) ----
    init_kernel<<<grd, blk>>>(2, nullptr);
    iter_kernel<<<grd, blk>>>(2, nullptr, 0, 0, 0, nullptr, 0);
    for (int k = 2; k <= 16; ++k) {
        int inSel  = (k & 1) ? 1 : 0;
        int outSel = (k & 1) ? 0 : 1;
        int doSum  = (k == 16) ? 1 : 0;
        iter_kernel<<<grd, blk>>>(inSel, nullptr, outSel, doSum, 3, tru, 3);
    }

    // ---- true skeleton (x = y_true) ----
    init_kernel<<<grd, blk>>>(3, tru);
    iter_kernel<<<grd, blk>>>(3, tru, 0, 0, 0, nullptr, 0);
    for (int k = 2; k <= 16; ++k) {
        int inSel  = (k & 1) ? 1 : 0;
        int outSel = (k & 1) ? 0 : 1;
        int doSum  = (k == 16) ? 1 : 0;
        iter_kernel<<<grd, blk>>>(inSel, nullptr, outSel, doSum, 2, nullptr, 5);
    }

    final_kernel<<<1, 1>>>(out);
}

// round 3
// speedup vs baseline: 2.6143x; 1.3707x over previous
#include <cuda_runtime.h>
#include <math.h>

#define VOL   128
#define VOL2  (VOL*VOL)
#define VOL3  (VOL*VOL*VOL)
#define NB    4
#define NVOX  (NB*VOL3)
#define OTY   26              // output rows per block tile (y)
#define NTY   5               // ceil(128/26)
#define ZSEG  7               // z segments per volume (140 blocks total = 1 wave)
#define ZLEN  19              // ceil(128/7); last segment shorter

#define PINF __int_as_float(0x7f800000)
#define NINF __int_as_float(0xff800000)

__device__ float g_yp[NVOX];
__device__ float g_imgA[NVOX];
__device__ float g_imgB[NVOX];
__device__ float g_skel[NVOX];
__device__ float g_acc[8];

__device__ __forceinline__ const float* pick(int sel, const float* ext) {
    if (sel == 0) return g_imgA;
    if (sel == 1) return g_imgB;
    if (sel == 2) return g_yp;
    return ext;
}

__device__ __forceinline__ float4 f4(float v) { return make_float4(v, v, v, v); }
__device__ __forceinline__ float4 vmin(float4 a, float4 b) {
    return make_float4(fminf(a.x,b.x), fminf(a.y,b.y), fminf(a.z,b.z), fminf(a.w,b.w));
}
__device__ __forceinline__ float4 vmax(float4 a, float4 b) {
    return make_float4(fmaxf(a.x,b.x), fmaxf(a.y,b.y), fmaxf(a.z,b.z), fmaxf(a.w,b.w));
}
__device__ __forceinline__ float4 vmin3(float4 a, float4 b, float4 c) { return vmin(vmin(a,b),c); }
__device__ __forceinline__ float4 vmax3(float4 a, float4 b, float4 c) { return vmax(vmax(a,b),c); }

__device__ __forceinline__ float4 hmin_shfl(float4 a, int tx) {
    float aL = __shfl_up_sync(0xffffffffu, a.w, 1);
    float aR = __shfl_down_sync(0xffffffffu, a.x, 1);
    if (tx == 0)  aL = a.x;
    if (tx == 31) aR = a.w;
    float m01 = fminf(a.x, a.y), m12 = fminf(a.y, a.z), m23 = fminf(a.z, a.w);
    return make_float4(fminf(aL, m01), fminf(m01, a.z), fminf(m12, a.w), fminf(m23, aR));
}
__device__ __forceinline__ float4 hmax_shfl(float4 a, int tx) {
    float aL = __shfl_up_sync(0xffffffffu, a.w, 1);
    float aR = __shfl_down_sync(0xffffffffu, a.x, 1);
    if (tx == 0)  aL = a.x;
    if (tx == 31) aR = a.w;
    float m01 = fmaxf(a.x, a.y), m12 = fmaxf(a.y, a.z), m23 = fmaxf(a.z, a.w);
    return make_float4(fmaxf(aL, m01), fmaxf(m01, a.z), fmaxf(m12, a.w), fmaxf(m23, aR));
}

__global__ void zero_acc_kernel() {
    if (threadIdx.x < 8) g_acc[threadIdx.x] = 0.f;
}

// ---------------------------------------------------------------------------
// prep: yp = sigmoid(pred); sums for dice
// ---------------------------------------------------------------------------
__global__ __launch_bounds__(256) void prep_kernel(const float* __restrict__ pred,
                                                   const float* __restrict__ tru) {
    __shared__ float sm[3][8];
    const float4* p4 = (const float4*)pred;
    const float4* t4 = (const float4*)tru;
    float4* y4 = (float4*)g_yp;
    int base = blockIdx.x * 1024 + threadIdx.x;
    float st = 0.f, sp = 0.f, stp = 0.f;
#pragma unroll
    for (int k = 0; k < 4; k++) {
        int i = base + k * 256;
        float4 t = t4[i];
        float4 x = p4[i];
        float4 p;
        p.x = 1.f / (1.f + __expf(-x.x));
        p.y = 1.f / (1.f + __expf(-x.y));
        p.z = 1.f / (1.f + __expf(-x.z));
        p.w = 1.f / (1.f + __expf(-x.w));
        y4[i] = p;
        st  += (t.x + t.y) + (t.z + t.w);
        sp  += (p.x + p.y) + (p.z + p.w);
        stp += (t.x*p.x + t.y*p.y) + (t.z*p.z + t.w*p.w);
    }
#pragma unroll
    for (int o = 16; o > 0; o >>= 1) {
        st  += __shfl_xor_sync(0xffffffffu, st,  o);
        sp  += __shfl_xor_sync(0xffffffffu, sp,  o);
        stp += __shfl_xor_sync(0xffffffffu, stp, o);
    }
    int w = threadIdx.x >> 5, lane = threadIdx.x & 31;
    if (lane == 0) { sm[0][w] = st; sm[1][w] = sp; sm[2][w] = stp; }
    __syncthreads();
    if (threadIdx.x == 0) {
        float a = 0.f, b = 0.f, c = 0.f;
#pragma unroll
        for (int i = 0; i < 8; i++) { a += sm[0][i]; b += sm[1][i]; c += sm[2][i]; }
        atomicAdd(&g_acc[0], a); atomicAdd(&g_acc[1], b); atomicAdd(&g_acc[2], c);
    }
}

// ---------------------------------------------------------------------------
// init: skel = relu(x - dilate(erode(x)))   float4 z-sweep, radius 2, 2 syncs/plane
// ---------------------------------------------------------------------------
__global__ __launch_bounds__(1024) void init_kernel(int inSel, const float* __restrict__ extIn) {
    __shared__ float4 As[32][32];
    __shared__ float4 Ms[32][32];
    const float* __restrict__ x = pick(inSel, extIn);

    const int tx = threadIdx.x, ty = threadIdx.y;
    const int b   = blockIdx.z;
    const int oz0 = blockIdx.y * ZLEN;
    const int oz1 = min(oz0 + ZLEN, VOL);
    const int gy  = blockIdx.x * OTY - 3 + ty;
    const bool vrow = (gy >= 0 && gy < VOL);
    const bool wr   = vrow && ty >= 3 && ty < 29;
    const int ym = ty > 0 ? ty - 1 : 0, yp = ty < 31 ? ty + 1 : 31;
    const int bOff = b * VOL3;
    const int rowOff = bOff + (vrow ? gy : 0) * VOL + tx * 4;

    float4 a_m1 = f4(PINF), a_m2 = f4(PINF), bxy_m1 = f4(PINF);
    float4 m_m1 = f4(NINF), m_m2 = f4(NINF);

    int z0 = oz0 - 2;
    float4 cur = f4(PINF);
    if (vrow && (unsigned)z0 < (unsigned)VOL)
        cur = *(const float4*)(x + z0 * VOL2 + rowOff);
    As[ty][tx] = cur;
    __syncthreads();

    for (int z = z0; z <= oz1 + 1; ++z) {
        float4 nxt = f4(PINF);
        if (vrow && (unsigned)(z + 1) < (unsigned)VOL)
            nxt = *(const float4*)(x + (z + 1) * VOL2 + rowOff);

        float4 up = As[ym][tx], dn = As[yp][tx];
        float4 h  = hmin_shfl(cur, tx);
        float4 bxy = vmin3(h, up, dn);
        float4 e1 = vmin3(a_m2, cur, bxy_m1);              // erode at z-1
        if (!vrow || (unsigned)(z - 1) >= (unsigned)VOL) e1 = f4(NINF);
        float4 hm = hmax_shfl(e1, tx);
        Ms[ty][tx] = hm;
        __syncthreads();                                   // S1: Ms visible, As reads done
        As[ty][tx] = nxt;
        float4 mxy = vmax3(hm, Ms[ym][tx], Ms[yp][tx]);    // 3x3 max of e1 at z-1
        int zo = z - 2;
        if (wr && zo >= oz0 && zo < oz1) {
            float4 openv = vmax3(m_m2, m_m1, mxy);
            float4 s;
            s.x = fmaxf(a_m2.x - openv.x, 0.f);
            s.y = fmaxf(a_m2.y - openv.y, 0.f);
            s.z = fmaxf(a_m2.z - openv.z, 0.f);
            s.w = fmaxf(a_m2.w - openv.w, 0.f);
            *(float4*)(g_skel + zo * VOL2 + rowOff) = s;
        }
        __syncthreads();                                   // S2: As(next) visible
        a_m2 = a_m1; a_m1 = cur; bxy_m1 = bxy;
        m_m2 = m_m1; m_m1 = mxy;
        cur = nxt;
    }
}

// ---------------------------------------------------------------------------
// iter: img' = erode(img); open = dilate(erode(img')); skel update
// float4 z-sweep pipeline, radius 3, 2 syncs/plane
// ---------------------------------------------------------------------------
__global__ __launch_bounds__(1024) void iter_kernel(
    int inSel, const float* __restrict__ extIn, int outSel,
    int doSum, int otherSel, const float* __restrict__ extOther, int accBase)
{
    __shared__ float4 As[32][32];
    __shared__ float4 Es[32][32];
    __shared__ float4 Ms[32][32];
    const float* __restrict__ imgIn = pick(inSel, extIn);
    float* imgOut = (outSel == 0) ? g_imgA : g_imgB;
    const float* __restrict__ other = pick(otherSel, extOther);

    const int tx = threadIdx.x, ty = threadIdx.y;
    const int b   = blockIdx.z;
    const int oz0 = blockIdx.y * ZLEN;
    const int oz1 = min(oz0 + ZLEN, VOL);
    const int gy  = blockIdx.x * OTY - 3 + ty;
    const bool vrow = (gy >= 0 && gy < VOL);
    const bool wr   = vrow && ty >= 3 && ty < 29;
    const int ym = ty > 0 ? ty - 1 : 0, yp = ty < 31 ? ty + 1 : 31;
    const int bOff = b * VOL3;
    const int rowOff = bOff + (vrow ? gy : 0) * VOL + tx * 4;

    float4 a_m1 = f4(PINF), a_m2 = f4(PINF), bxy_m1 = f4(PINF);
    float4 e1_m1 = f4(PINF), e1_m2 = f4(PINF), cxy_m1 = f4(PINF);
    float4 m_m1 = f4(NINF), m_m2 = f4(NINF);
    float sumS = 0.f, sumC = 0.f;

    int z0 = oz0 - 3;
    float4 cur = f4(PINF);
    if (vrow && (unsigned)z0 < (unsigned)VOL)
        cur = *(const float4*)(imgIn + z0 * VOL2 + rowOff);
    As[ty][tx] = cur;
    __syncthreads();

    for (int z = z0; z <= oz1 + 2; ++z) {
        float4 nxt = f4(PINF);
        if (vrow && (unsigned)(z + 1) < (unsigned)VOL)
            nxt = *(const float4*)(imgIn + (z + 1) * VOL2 + rowOff);

        // stage 1: erode(img) at z-1 (As holds plane z)
        float4 up = As[ym][tx], dn = As[yp][tx];
        float4 h  = hmin_shfl(cur, tx);
        float4 bxy = vmin3(h, up, dn);
        float4 e1 = vmin3(a_m2, cur, bxy_m1);
        if (!vrow || (unsigned)(z - 1) >= (unsigned)VOL) e1 = f4(PINF);
        Es[ty][tx] = e1;
        __syncthreads();                                   // S1: Es visible, As reads done

        // stage 2: erode(e1) at z-2
        float4 upe = Es[ym][tx], dne = Es[yp][tx];
        float4 h2  = hmin_shfl(e1, tx);
        float4 cxy = vmin3(h2, upe, dne);
        float4 e2 = vmin3(e1_m2, e1, cxy_m1);
        if (!vrow || (unsigned)(z - 2) >= (unsigned)VOL) e2 = f4(NINF);

        // stage 3: 3x3 in-plane max of e2
        float4 hm = hmax_shfl(e2, tx);
        Ms[ty][tx] = hm;
        As[ty][tx] = nxt;                                  // safe: all passed S1
        __syncthreads();                                   // S2: Ms + As(next) visible
        float4 mxy = vmax3(hm, Ms[ym][tx], Ms[yp][tx]);

        int zo = z - 3;
        if (wr && zo >= oz0 && zo < oz1) {
            float4 openv = vmax3(m_m2, m_m1, mxy);          // dilate(e2) at zo
            float4 imgN = e1_m2;                            // erode(img) at zo
            float4 delta;
            delta.x = fmaxf(imgN.x - openv.x, 0.f);
            delta.y = fmaxf(imgN.y - openv.y, 0.f);
            delta.z = fmaxf(imgN.z - openv.z, 0.f);
            delta.w = fmaxf(imgN.w - openv.w, 0.f);
            int gi = zo * VOL2 + rowOff;
            float4 s = *(float4*)(g_skel + gi);
            s.x += fmaxf(fmaf(-s.x, delta.x, delta.x), 0.f);
            s.y += fmaxf(fmaf(-s.y, delta.y, delta.y), 0.f);
            s.z += fmaxf(fmaf(-s.z, delta.z, delta.z), 0.f);
            s.w += fmaxf(fmaf(-s.w, delta.w, delta.w), 0.f);
            *(float4*)(g_skel + gi) = s;
            *(float4*)(imgOut + gi) = imgN;
            if (doSum) {
                float4 o = *(const float4*)(other + gi);
                sumS += (s.x + s.y) + (s.z + s.w);
                sumC += (s.x*o.x + s.y*o.y) + (s.z*o.z + s.w*o.w);
            }
        }
        a_m2 = a_m1; a_m1 = cur; bxy_m1 = bxy;
        e1_m2 = e1_m1; e1_m1 = e1; cxy_m1 = cxy;
        m_m2 = m_m1; m_m1 = mxy;
        cur = nxt;
    }

    if (doSum) {
        __syncthreads();
#pragma unroll
        for (int o = 16; o > 0; o >>= 1) {
            sumS += __shfl_xor_sync(0xffffffffu, sumS, o);
            sumC += __shfl_xor_sync(0xffffffffu, sumC, o);
        }
        int tid = ty * 32 + tx;
        int w = tid >> 5, lane = tid & 31;
        float* red = (float*)As;
        if (lane == 0) { red[w] = sumS; red[32 + w] = sumC; }
        __syncthreads();
        if (w == 0) {
            float s = red[lane], c = red[32 + lane];
#pragma unroll
            for (int o = 16; o > 0; o >>= 1) {
                s += __shfl_xor_sync(0xffffffffu, s, o);
                c += __shfl_xor_sync(0xffffffffu, c, o);
            }
            if (lane == 0) {
                atomicAdd(&g_acc[accBase], s);
                atomicAdd(&g_acc[accBase + 1], c);
            }
        }
    }
}

__global__ void final_kernel(float* out) {
    float st = g_acc[0], sp = g_acc[1], stp = g_acc[2];
    float skp = g_acc[3], skpt = g_acc[4], skt = g_acc[5], sktp = g_acc[6];
    float dice = 1.f - (2.f * stp + 1.f) / (st + sp + 1.f);
    float tprec = (skpt + 1.f) / (skp + 1.f);
    float tsens = (sktp + 1.f) / (skt + 1.f);
    float cl = 1.f - 2.f * (tprec * tsens) / (tprec + tsens);
    out[0] = 0.7f * dice + 0.3f * cl;
}

extern "C" void kernel_launch(void* const* d_in, const int* in_sizes, int n_in,
                              void* d_out, int out_size) {
    const float* pred = (const float*)d_in[0];
    const float* tru  = (const float*)d_in[1];
    float* out = (float*)d_out;

    dim3 blk(32, 32);
    dim3 grd(NTY, ZSEG, NB);

    zero_acc_kernel<<<1, 32>>>();
    prep_kernel<<<NVOX / 4096, 256>>>(pred, tru);

    // ---- pred skeleton (x = sigmoid(pred) in g_yp) ----
    init_kernel<<<grd, blk>>>(2, nullptr);
    iter_kernel<<<grd, blk>>>(2, nullptr, 0, 0, 0, nullptr, 0);
    for (int k = 2; k <= 16; ++k) {
        int inSel  = (k & 1) ? 1 : 0;
        int outSel = (k & 1) ? 0 : 1;
        int doSum  = (k == 16) ? 1 : 0;
        iter_kernel<<<grd, blk>>>(inSel, nullptr, outSel, doSum, 3, tru, 3);
    }

    // ---- true skeleton (x = y_true) ----
    init_kernel<<<grd, blk>>>(3, tru);
    iter_kernel<<<grd, blk>>>(3, tru, 0, 0, 0, nullptr, 0);
    for (int k = 2; k <= 16; ++k) {
        int inSel  = (k & 1) ? 1 : 0;
        int outSel = (k & 1) ? 0 : 1;
        int doSum  = (k == 16) ? 1 : 0;
        iter_kernel<<<grd, blk>>>(inSel, nullptr, outSel, doSum, 2, nullptr, 5);
    }

    final_kernel<<<1, 1>>>(out);
}